// round 8
// baseline (speedup 1.0000x reference)
#include <cuda_runtime.h>
#include <math.h>
#include <float.h>

#define BB 16
#define TT 512
#define DD 512

typedef unsigned long long ull;
__device__ __forceinline__ ull umax64(ull a, ull b) { return a > b ? a : b; }
__device__ __forceinline__ ull umin64(ull a, ull b) { return a < b ? a : b; }

// ---------------- scratch (static __device__ — no allocations) ----------------
__device__ float g_xtr[BB * DD];                    // x_trans (before +b_lin)
__device__ int   g_done = 0;                        // last-block detector (reset each run)

// ---------------- fused: 4 series per block, 2 packed real FFTs (radix-4),
// ---------------- + last-block inline router ----------------
__global__ void __launch_bounds__(256) k_fused(const float* __restrict__ x,
                                               const float* __restrict__ W_trend,
                                               const float* __restrict__ b_trend,
                                               const float* __restrict__ W_lin,
                                               const float* __restrict__ noise,
                                               const float* __restrict__ W_r,
                                               const float* __restrict__ b_r,
                                               const float* __restrict__ W_noise,
                                               const float* __restrict__ b_noise,
                                               const float* __restrict__ b_lin,
                                               float* __restrict__ out) {
    __shared__ float s_re[2][1024];     // [pingpong][fft*512 + idx]
    __shared__ float s_im[2][1024];
    __shared__ float s_cos[512];
    __shared__ float s_sin[512];
    __shared__ float s_x[4][512];
    __shared__ float s_cs[4][513];
    __shared__ int   s_wk[4][4];
    __shared__ float s_wr[4][4], s_wi[4][4];
    __shared__ float s_red[4][8];
    __shared__ int   s_last;

    int tid = threadIdx.x;
    int lane = tid & 31, w = tid >> 5;
    int bidx = blockIdx.x;
    int b  = bidx >> 7;                 // 128 blocks per batch (512/4)
    int d0 = (bidx & 127) << 2;

    // issue strided global loads first (latency hidden by trig below)
    const float* xp = x + ((size_t)b * TT + tid) * DD + d0;
    float4 v0 = *(const float4*)xp;
    float4 v1 = *(const float4*)(xp + (size_t)256 * DD);

    // trig table: one sincospif; second half via cos(pi+a) = -cos(a)
    {
        float s0, c0;
        sincospif((float)tid * (1.0f / 256.0f), &s0, &c0);
        s_cos[tid] = c0; s_sin[tid] = s0;
        s_cos[tid + 256] = -c0; s_sin[tid + 256] = -s0;
    }

    // stash x; pack fft0 = x(d0) + i x(d0+1), fft1 = x(d0+2) + i x(d0+3)
    s_x[0][tid] = v0.x; s_x[1][tid] = v0.y; s_x[2][tid] = v0.z; s_x[3][tid] = v0.w;
    s_x[0][tid + 256] = v1.x; s_x[1][tid + 256] = v1.y;
    s_x[2][tid + 256] = v1.z; s_x[3][tid + 256] = v1.w;
    s_re[0][tid]       = v0.x; s_im[0][tid]       = v0.y;
    s_re[0][tid + 256] = v1.x; s_im[0][tid + 256] = v1.y;
    s_re[0][512 + tid]       = v0.z; s_im[0][512 + tid]       = v0.w;
    s_re[0][512 + tid + 256] = v1.z; s_im[0][512 + tid + 256] = v1.w;

    // ---- 4 radix-4 Stockham stages (Ns = 1,4,16,64), 2 FFTs in parallel ----
    int cur = 0;
    #pragma unroll
    for (int st = 0; st < 4; st++) {
        int Ns = 1 << (2 * st);
        int shiftm = 7 - 2 * st;         // twiddle idx = k * (128/Ns)
        __syncthreads();
        int f = tid >> 7;                // fft id
        int j = tid & 127;
        int k = j & (Ns - 1);
        int base = f << 9;
        float x0r = s_re[cur][base + j],       x0i = s_im[cur][base + j];
        float x1r = s_re[cur][base + j + 128], x1i = s_im[cur][base + j + 128];
        float x2r = s_re[cur][base + j + 256], x2i = s_im[cur][base + j + 256];
        float x3r = s_re[cur][base + j + 384], x3i = s_im[cur][base + j + 384];
        int m = k << shiftm;
        float c1w = s_cos[m],     s1w = s_sin[m];
        float c2w = s_cos[2 * m], s2w = s_sin[2 * m];
        float c3w = s_cos[3 * m], s3w = s_sin[3 * m];
        // t = W*x, W = (c, -s)
        float t1r = c1w * x1r + s1w * x1i, t1i = c1w * x1i - s1w * x1r;
        float t2r = c2w * x2r + s2w * x2i, t2i = c2w * x2i - s2w * x2r;
        float t3r = c3w * x3r + s3w * x3i, t3i = c3w * x3i - s3w * x3r;
        float y0r = x0r + t1r + t2r + t3r, y0i = x0i + t1i + t2i + t3i;
        float y2r = x0r - t1r + t2r - t3r, y2i = x0i - t1i + t2i - t3i;
        float y1r = x0r + t1i - t2r - t3i, y1i = x0i - t1r - t2i + t3r;
        float y3r = x0r - t1i - t2r + t3i, y3i = x0i + t1r - t2i - t3r;
        int o = base + 4 * j - 3 * k;
        int nxt = cur ^ 1;
        s_re[nxt][o]          = y0r; s_im[nxt][o]          = y0i;
        s_re[nxt][o + Ns]     = y1r; s_im[nxt][o + Ns]     = y1i;
        s_re[nxt][o + 2 * Ns] = y2r; s_im[nxt][o + 2 * Ns] = y2i;
        s_re[nxt][o + 3 * Ns] = y3r; s_im[nxt][o + 3 * Ns] = y3i;
        cur = nxt;
    }
    // ---- final radix-2 stage (Ns = 256), each thread does both FFTs ----
    __syncthreads();
    {
        int k = tid;
        float cw = s_cos[k], sw = s_sin[k];
        int nxt = cur ^ 1;
        #pragma unroll
        for (int f = 0; f < 2; f++) {
            int base = f << 9;
            float ar = s_re[cur][base + k],       ai = s_im[cur][base + k];
            float br = s_re[cur][base + k + 256], bi = s_im[cur][base + k + 256];
            float tr = cw * br + sw * bi, ti = cw * bi - sw * br;
            s_re[nxt][base + k]       = ar + tr; s_im[nxt][base + k]       = ai + ti;
            s_re[nxt][base + k + 256] = ar - tr; s_im[nxt][base + k + 256] = ai - ti;
        }
        cur = nxt;                        // final spectrum in buf 1
    }
    __syncthreads();

    // ---- unpack: spectra of 4 series into buf0 ----
    if (tid >= 1) {
        int k = tid, mk = 512 - tid;
        #pragma unroll
        for (int f = 0; f < 2; f++) {
            int base = f << 9;
            float Zr = s_re[1][base + k],  Zi = s_im[1][base + k];
            float Mr = s_re[1][base + mk], Mi = s_im[1][base + mk];
            float Xar = 0.5f * (Zr + Mr), Xai = 0.5f * (Zi - Mi);
            float Xbr = 0.5f * (Zi + Mi), Xbi = 0.5f * (Mr - Zr);
            int sA = 2 * f, sB = 2 * f + 1;
            s_re[0][sA * 256 + k] = Xar; s_im[0][sA * 256 + k] = Xai;
            s_re[0][sB * 256 + k] = Xbr; s_im[0][sB * 256 + k] = Xbi;
        }
    }
    __syncthreads();

    // ---- warp top-4 per series (warps 0..3), key = amp_bits<<32 | (511-k) ----
    if (w < 4) {
        const float* Xr = &s_re[0][w * 256];
        const float* Xi = &s_im[0][w * 256];
        ull c0 = 0, c1 = 0, c2 = 0, c3 = 0;
        #pragma unroll
        for (int j = 0; j < 8; j++) {
            int k = lane + 32 * j;
            float xr = Xr[k], xi = Xi[k];
            float a = xr * xr + xi * xi;
            ull p = (k == 0) ? 0ull
                  : (((ull)__float_as_uint(a) << 32) | (ull)(511 - k));
            ull t;
            t = umin64(c0, p); c0 = umax64(c0, p); p = t;
            t = umin64(c1, p); c1 = umax64(c1, p); p = t;
            t = umin64(c2, p); c2 = umax64(c2, p); p = t;
            c3 = umax64(c3, p);
        }
        #pragma unroll
        for (int off = 16; off; off >>= 1) {
            ull o0 = __shfl_xor_sync(0xffffffffu, c0, off);
            ull o1 = __shfl_xor_sync(0xffffffffu, c1, off);
            ull o2 = __shfl_xor_sync(0xffffffffu, c2, off);
            ull o3 = __shfl_xor_sync(0xffffffffu, c3, off);
            bool mf = c0 > o0;
            ull u0 = mf ? c0 : o0, u1 = mf ? c1 : o1, u2 = mf ? c2 : o2, u3 = mf ? c3 : o3;
            ull v0_ = mf ? o0 : c0, v1_ = mf ? o1 : c1, v2_ = mf ? o2 : c2, v3_ = mf ? o3 : c3;
            ull A0 = umax64(u0, v3_), A1 = umax64(u1, v2_);
            ull A2 = umax64(u2, v1_), A3 = umax64(u3, v0_);
            ull B0 = umax64(A0, A2), B2 = umin64(A0, A2);
            ull B1 = umax64(A1, A3), B3 = umin64(A1, A3);
            c0 = umax64(B0, B1); c1 = umin64(B0, B1);
            c2 = umax64(B2, B3); c3 = umin64(B2, B3);
        }
        if (lane == 0) {
            int k0 = 511 - (int)(c0 & 0xffffffffull);
            int k1 = 511 - (int)(c1 & 0xffffffffull);
            int k2 = 511 - (int)(c2 & 0xffffffffull);
            int k3 = 511 - (int)(c3 & 0xffffffffull);
            s_wk[w][0] = k0; s_wr[w][0] = Xr[k0]; s_wi[w][0] = Xi[k0];
            s_wk[w][1] = k1; s_wr[w][1] = Xr[k1]; s_wi[w][1] = Xi[k1];
            s_wk[w][2] = k2; s_wr[w][2] = Xr[k2]; s_wi[w][2] = Xi[k2];
            s_wk[w][3] = k3; s_wr[w][3] = Xr[k3]; s_wi[w][3] = Xi[k3];
        }
    }
    __syncthreads();

    // rem layout in buf1: s0 -> s_re[1][t], s1 -> s_re[1][512+t], s2 -> s_im[1][t], s3 -> s_im[1][512+t]
    #pragma unroll
    for (int s = 0; s < 4; s++) {
        int   kk0 = s_wk[s][0], kk1 = s_wk[s][1], kk2 = s_wk[s][2], kk3 = s_wk[s][3];
        float r0 = s_wr[s][0], r1 = s_wr[s][1], r2 = s_wr[s][2], r3 = s_wr[s][3];
        float i0 = s_wi[s][0], i1 = s_wi[s][1], i2 = s_wi[s][2], i3 = s_wi[s][3];
        float* remp = (s & 2) ? &s_im[1][(s & 1) * 512] : &s_re[1][(s & 1) * 512];
        #pragma unroll
        for (int tt = 0; tt < 2; tt++) {
            int t = tid + tt * 256;
            int a0 = (kk0 * t) & 511, a1 = (kk1 * t) & 511;
            int a2 = (kk2 * t) & 511, a3 = (kk3 * t) & 511;
            float se = r0 * s_cos[a0] - i0 * s_sin[a0]
                     + r1 * s_cos[a1] - i1 * s_sin[a1]
                     + r2 * s_cos[a2] - i2 * s_sin[a2]
                     + r3 * s_cos[a3] - i3 * s_sin[a3];
            remp[t] = s_x[s][t] - se * (2.0f / 512.0f);
        }
    }
    __syncthreads();

    // ---- 4 parallel exclusive cumsums (warp w -> series w) ----
    if (w < 4) {
        const float* rm = (w & 2) ? &s_im[1][(w & 1) * 512] : &s_re[1][(w & 1) * 512];
        float* cs = s_cs[w];
        int base = lane * 16;
        float run = 0.f, pref[16];
        #pragma unroll
        for (int i = 0; i < 16; i++) { pref[i] = run; run += rm[base + i]; }
        float inc = run;
        #pragma unroll
        for (int sft = 1; sft < 32; sft <<= 1) {
            float v = __shfl_up_sync(0xffffffffu, inc, sft);
            if (lane >= sft) inc += v;
        }
        float excl = inc - run;
        #pragma unroll
        for (int i = 0; i < 16; i++) cs[base + i] = excl + pref[i];
        if (lane == 31) cs[512] = inc;
    }
    __syncthreads();

    // ---- trend + W_lin reduce, 4 series ----
    float Wt[6], bt[6];
    #pragma unroll
    for (int j = 0; j < 6; j++) { Wt[j] = W_trend[j]; bt[j] = b_trend[j]; }
    const int   KSv[6] = {4, 8, 12, 16, 24, 32};
    const float inv[6] = {0.25f, 0.125f, 1.f / 12.f, 0.0625f, 1.f / 24.f, 0.03125f};
    float wl0 = W_lin[tid], wl1 = W_lin[tid + 256];

    float accv[4];
    #pragma unroll
    for (int s = 0; s < 4; s++) {
        const float* rem_s = (s & 2) ? &s_im[1][(s & 1) * 512] : &s_re[1][(s & 1) * 512];
        const float* cs_s  = s_cs[s];
        const float* x_s   = s_x[s];
        float rem0 = rem_s[0], remL = rem_s[511];
        float acc = 0.f;
        #pragma unroll
        for (int tt = 0; tt < 2; tt++) {
            int t = tid + tt * 256;
            float rem = rem_s[t];
            float mm[6], lg[6];
            float mx = -FLT_MAX;
            #pragma unroll
            for (int j = 0; j < 6; j++) {
                int k = KSv[j];
                int lo = t - (k >> 1), hi = t + (k >> 1) - 1;
                int clo = lo < 0 ? 0 : lo;
                int chi = hi > 511 ? 511 : hi;
                float ssum = cs_s[chi + 1] - cs_s[clo];
                if (lo < 0)   ssum += (float)(-lo) * rem0;
                if (hi > 511) ssum += (float)(hi - 511) * remL;
                mm[j] = ssum * inv[j];
                float l = fmaf(rem, Wt[j], bt[j]);
                lg[j] = l;
                mx = fmaxf(mx, l);
            }
            float es = 0.f, ws = 0.f;
            #pragma unroll
            for (int j = 0; j < 6; j++) {
                float e = __expf(lg[j] - mx);
                es += e;
                ws = fmaf(e, mm[j], ws);
            }
            float trend = ws / es;
            float xsum = 2.0f * x_s[t] - rem + trend;
            acc = fmaf(xsum, (tt ? wl1 : wl0), acc);
        }
        accv[s] = acc;
    }

    #pragma unroll
    for (int o = 16; o > 0; o >>= 1) {
        accv[0] += __shfl_down_sync(0xffffffffu, accv[0], o);
        accv[1] += __shfl_down_sync(0xffffffffu, accv[1], o);
        accv[2] += __shfl_down_sync(0xffffffffu, accv[2], o);
        accv[3] += __shfl_down_sync(0xffffffffu, accv[3], o);
    }
    if (lane == 0) {
        s_red[0][w] = accv[0]; s_red[1][w] = accv[1];
        s_red[2][w] = accv[2]; s_red[3][w] = accv[3];
    }
    __syncthreads();
    if (tid < 4) {
        float s = 0.f;
        #pragma unroll
        for (int ww = 0; ww < 8; ww++) s += s_red[tid][ww];
        g_xtr[blockIdx.x * 4 + tid] = s;
    }

    // ---- last-block inline router ----
    __threadfence();
    __syncthreads();
    if (tid == 0) {
        int prev = atomicAdd(&g_done, 1);
        s_last = (prev == (int)gridDim.x - 1);
    }
    __syncthreads();
    if (!s_last) return;
    __threadfence();                         // acquire: see all g_xtr writes

    __shared__ float r_logit[16][8];
    if (tid < 128) {
        int bb = tid >> 3, m = tid & 7;
        const float* xt = g_xtr + bb * DD;
        float blin = b_lin[0];
        float p = 0.f, pn = 0.f;
        #pragma unroll 8
        for (int d = 0; d < 512; d++) {
            float v = xt[d] + blin;
            p  = fmaf(v, W_r[d * 8 + m], p);
            pn = fmaf(v, W_noise[d * 8 + m], pn);
        }
        float base = p + b_r[m];
        float nl = pn + b_noise[m];
        float ns = log1pf(expf(-fabsf(nl))) + fmaxf(nl, 0.f);   // softplus
        r_logit[bb][m] = base + noise[bb * 8 + m] * ns;
    }
    __syncthreads();
    if (tid < 16) {
        float lg[8], mx = -FLT_MAX;
        #pragma unroll
        for (int i = 0; i < 8; i++) { lg[i] = r_logit[tid][i]; mx = fmaxf(mx, lg[i]); }
        float es = 0.f, pw[8];
        #pragma unroll
        for (int i = 0; i < 8; i++) { pw[i] = expf(lg[i] - mx); es += pw[i]; }
        #pragma unroll
        for (int i = 0; i < 8; i++) pw[i] /= es;
        #pragma unroll
        for (int i = 0; i < 8; i++) {
            int rank = 0;
            #pragma unroll
            for (int j = 0; j < 8; j++)
                if (pw[j] > pw[i] || (pw[j] == pw[i] && j < i)) rank++;
            out[tid * 8 + i] = (rank < 4) ? pw[i] : 0.f;
        }
    }
    if (tid == 0) g_done = 0;                // reset for next graph replay
}

// ---------------- launch ----------------
extern "C" void kernel_launch(void* const* d_in, const int* in_sizes, int n_in,
                              void* d_out, int out_size) {
    const float* x       = (const float*)d_in[0];
    const float* noise   = (const float*)d_in[1];
    const float* W_r     = (const float*)d_in[2];
    const float* b_r     = (const float*)d_in[3];
    const float* W_noise = (const float*)d_in[4];
    const float* b_noise = (const float*)d_in[5];
    const float* W_trend = (const float*)d_in[6];
    const float* b_trend = (const float*)d_in[7];
    const float* W_lin   = (const float*)d_in[8];
    const float* b_lin   = (const float*)d_in[9];
    float* out = (float*)d_out;

    k_fused<<<BB * DD / 4, 256>>>(x, W_trend, b_trend, W_lin,
                                  noise, W_r, b_r, W_noise, b_noise, b_lin, out);
}

// round 9
// speedup vs baseline: 1.3920x; 1.3920x over previous
#include <cuda_runtime.h>
#include <math.h>
#include <float.h>

#define BB 16
#define TT 512
#define DD 512

typedef unsigned long long ull;
__device__ __forceinline__ ull umax64(ull a, ull b) { return a > b ? a : b; }
__device__ __forceinline__ ull umin64(ull a, ull b) { return a < b ? a : b; }

// ---------------- scratch (static __device__ — no allocations) ----------------
__device__ float g_xtr[BB * DD];                    // x_trans (before +b_lin)

// ---------------- fused: 4 series per block, 2 packed real FFTs (radix-4) ----------------
__global__ void __launch_bounds__(256, 5) k_fused(const float* __restrict__ x,
                                                  const float* __restrict__ W_trend,
                                                  const float* __restrict__ b_trend,
                                                  const float* __restrict__ W_lin) {
    __shared__ float s_re[2][1024];     // [pingpong][fft*512 + idx]; buf0 reused for cumsums
    __shared__ float s_im[2][1024];
    __shared__ float s_cos[512];
    __shared__ float s_sin[512];
    __shared__ float s_x[4][512];
    __shared__ int   s_wk[4][4];
    __shared__ float s_wr[4][4], s_wi[4][4];
    __shared__ float s_red[4][8];
    __shared__ float s_tot[4];          // cumsum totals (cs[512])

    int tid = threadIdx.x;
    int lane = tid & 31, w = tid >> 5;
    int bidx = blockIdx.x;
    int b  = bidx >> 7;                 // 128 blocks per batch (512/4)
    int d0 = (bidx & 127) << 2;

    // issue strided global loads first (latency hidden by trig below)
    const float* xp = x + ((size_t)b * TT + tid) * DD + d0;
    float4 v0 = *(const float4*)xp;
    float4 v1 = *(const float4*)(xp + (size_t)256 * DD);

    // trig table: one sincospif; second half via cos(pi+a) = -cos(a)
    {
        float s0, c0;
        sincospif((float)tid * (1.0f / 256.0f), &s0, &c0);
        s_cos[tid] = c0; s_sin[tid] = s0;
        s_cos[tid + 256] = -c0; s_sin[tid + 256] = -s0;
    }

    // stash x; pack fft0 = x(d0) + i x(d0+1), fft1 = x(d0+2) + i x(d0+3)
    s_x[0][tid] = v0.x; s_x[1][tid] = v0.y; s_x[2][tid] = v0.z; s_x[3][tid] = v0.w;
    s_x[0][tid + 256] = v1.x; s_x[1][tid + 256] = v1.y;
    s_x[2][tid + 256] = v1.z; s_x[3][tid + 256] = v1.w;
    s_re[0][tid]       = v0.x; s_im[0][tid]       = v0.y;
    s_re[0][tid + 256] = v1.x; s_im[0][tid + 256] = v1.y;
    s_re[0][512 + tid]       = v0.z; s_im[0][512 + tid]       = v0.w;
    s_re[0][512 + tid + 256] = v1.z; s_im[0][512 + tid + 256] = v1.w;

    // ---- 4 radix-4 Stockham stages (Ns = 1,4,16,64), 2 FFTs in parallel ----
    int cur = 0;
    #pragma unroll
    for (int st = 0; st < 4; st++) {
        int Ns = 1 << (2 * st);
        int shiftm = 7 - 2 * st;         // twiddle idx = k * (128/Ns)
        __syncthreads();
        int f = tid >> 7;                // fft id
        int j = tid & 127;
        int k = j & (Ns - 1);
        int base = f << 9;
        float x0r = s_re[cur][base + j],       x0i = s_im[cur][base + j];
        float x1r = s_re[cur][base + j + 128], x1i = s_im[cur][base + j + 128];
        float x2r = s_re[cur][base + j + 256], x2i = s_im[cur][base + j + 256];
        float x3r = s_re[cur][base + j + 384], x3i = s_im[cur][base + j + 384];
        int m = k << shiftm;
        float c1w = s_cos[m],     s1w = s_sin[m];
        float c2w = s_cos[2 * m], s2w = s_sin[2 * m];
        float c3w = s_cos[3 * m], s3w = s_sin[3 * m];
        // t = W*x, W = (c, -s)
        float t1r = c1w * x1r + s1w * x1i, t1i = c1w * x1i - s1w * x1r;
        float t2r = c2w * x2r + s2w * x2i, t2i = c2w * x2i - s2w * x2r;
        float t3r = c3w * x3r + s3w * x3i, t3i = c3w * x3i - s3w * x3r;
        float y0r = x0r + t1r + t2r + t3r, y0i = x0i + t1i + t2i + t3i;
        float y2r = x0r - t1r + t2r - t3r, y2i = x0i - t1i + t2i - t3i;
        float y1r = x0r + t1i - t2r - t3i, y1i = x0i - t1r - t2i + t3r;
        float y3r = x0r - t1i - t2r + t3i, y3i = x0i + t1r - t2i - t3r;
        int o = base + 4 * j - 3 * k;
        int nxt = cur ^ 1;
        s_re[nxt][o]          = y0r; s_im[nxt][o]          = y0i;
        s_re[nxt][o + Ns]     = y1r; s_im[nxt][o + Ns]     = y1i;
        s_re[nxt][o + 2 * Ns] = y2r; s_im[nxt][o + 2 * Ns] = y2i;
        s_re[nxt][o + 3 * Ns] = y3r; s_im[nxt][o + 3 * Ns] = y3i;
        cur = nxt;
    }
    // ---- final radix-2 stage (Ns = 256), each thread does both FFTs ----
    __syncthreads();
    {
        int k = tid;
        float cw = s_cos[k], sw = s_sin[k];
        int nxt = cur ^ 1;
        #pragma unroll
        for (int f = 0; f < 2; f++) {
            int base = f << 9;
            float ar = s_re[cur][base + k],       ai = s_im[cur][base + k];
            float br = s_re[cur][base + k + 256], bi = s_im[cur][base + k + 256];
            float tr = cw * br + sw * bi, ti = cw * bi - sw * br;
            s_re[nxt][base + k]       = ar + tr; s_im[nxt][base + k]       = ai + ti;
            s_re[nxt][base + k + 256] = ar - tr; s_im[nxt][base + k + 256] = ai - ti;
        }
        cur = nxt;                        // final spectrum in buf 1
    }
    __syncthreads();

    // ---- unpack: spectra of 4 series into buf0 ----
    if (tid >= 1) {
        int k = tid, mk = 512 - tid;
        #pragma unroll
        for (int f = 0; f < 2; f++) {
            int base = f << 9;
            float Zr = s_re[1][base + k],  Zi = s_im[1][base + k];
            float Mr = s_re[1][base + mk], Mi = s_im[1][base + mk];
            float Xar = 0.5f * (Zr + Mr), Xai = 0.5f * (Zi - Mi);
            float Xbr = 0.5f * (Zi + Mi), Xbi = 0.5f * (Mr - Zr);
            int sA = 2 * f, sB = 2 * f + 1;
            s_re[0][sA * 256 + k] = Xar; s_im[0][sA * 256 + k] = Xai;
            s_re[0][sB * 256 + k] = Xbr; s_im[0][sB * 256 + k] = Xbi;
        }
    }
    __syncthreads();

    // ---- warp top-4 per series (warps 0..3), key = amp_bits<<32 | (511-k) ----
    if (w < 4) {
        const float* Xr = &s_re[0][w * 256];
        const float* Xi = &s_im[0][w * 256];
        ull c0 = 0, c1 = 0, c2 = 0, c3 = 0;
        #pragma unroll
        for (int j = 0; j < 8; j++) {
            int k = lane + 32 * j;
            float xr = Xr[k], xi = Xi[k];
            float a = xr * xr + xi * xi;
            ull p = (k == 0) ? 0ull
                  : (((ull)__float_as_uint(a) << 32) | (ull)(511 - k));
            ull t;
            t = umin64(c0, p); c0 = umax64(c0, p); p = t;
            t = umin64(c1, p); c1 = umax64(c1, p); p = t;
            t = umin64(c2, p); c2 = umax64(c2, p); p = t;
            c3 = umax64(c3, p);
        }
        #pragma unroll
        for (int off = 16; off; off >>= 1) {
            ull o0 = __shfl_xor_sync(0xffffffffu, c0, off);
            ull o1 = __shfl_xor_sync(0xffffffffu, c1, off);
            ull o2 = __shfl_xor_sync(0xffffffffu, c2, off);
            ull o3 = __shfl_xor_sync(0xffffffffu, c3, off);
            bool mf = c0 > o0;
            ull u0 = mf ? c0 : o0, u1 = mf ? c1 : o1, u2 = mf ? c2 : o2, u3 = mf ? c3 : o3;
            ull v0_ = mf ? o0 : c0, v1_ = mf ? o1 : c1, v2_ = mf ? o2 : c2, v3_ = mf ? o3 : c3;
            ull A0 = umax64(u0, v3_), A1 = umax64(u1, v2_);
            ull A2 = umax64(u2, v1_), A3 = umax64(u3, v0_);
            ull B0 = umax64(A0, A2), B2 = umin64(A0, A2);
            ull B1 = umax64(A1, A3), B3 = umin64(A1, A3);
            c0 = umax64(B0, B1); c1 = umin64(B0, B1);
            c2 = umax64(B2, B3); c3 = umin64(B2, B3);
        }
        if (lane == 0) {
            int k0 = 511 - (int)(c0 & 0xffffffffull);
            int k1 = 511 - (int)(c1 & 0xffffffffull);
            int k2 = 511 - (int)(c2 & 0xffffffffull);
            int k3 = 511 - (int)(c3 & 0xffffffffull);
            s_wk[w][0] = k0; s_wr[w][0] = Xr[k0]; s_wi[w][0] = Xi[k0];
            s_wk[w][1] = k1; s_wr[w][1] = Xr[k1]; s_wi[w][1] = Xi[k1];
            s_wk[w][2] = k2; s_wr[w][2] = Xr[k2]; s_wi[w][2] = Xi[k2];
            s_wk[w][3] = k3; s_wr[w][3] = Xr[k3]; s_wi[w][3] = Xi[k3];
        }
    }
    __syncthreads();

    // rem layout in buf1: s0 -> s_re[1][t], s1 -> s_re[1][512+t], s2 -> s_im[1][t], s3 -> s_im[1][512+t]
    #pragma unroll
    for (int s = 0; s < 4; s++) {
        int   kk0 = s_wk[s][0], kk1 = s_wk[s][1], kk2 = s_wk[s][2], kk3 = s_wk[s][3];
        float r0 = s_wr[s][0], r1 = s_wr[s][1], r2 = s_wr[s][2], r3 = s_wr[s][3];
        float i0 = s_wi[s][0], i1 = s_wi[s][1], i2 = s_wi[s][2], i3 = s_wi[s][3];
        float* remp = (s & 2) ? &s_im[1][(s & 1) * 512] : &s_re[1][(s & 1) * 512];
        #pragma unroll
        for (int tt = 0; tt < 2; tt++) {
            int t = tid + tt * 256;
            int a0 = (kk0 * t) & 511, a1 = (kk1 * t) & 511;
            int a2 = (kk2 * t) & 511, a3 = (kk3 * t) & 511;
            float se = r0 * s_cos[a0] - i0 * s_sin[a0]
                     + r1 * s_cos[a1] - i1 * s_sin[a1]
                     + r2 * s_cos[a2] - i2 * s_sin[a2]
                     + r3 * s_cos[a3] - i3 * s_sin[a3];
            remp[t] = s_x[s][t] - se * (2.0f / 512.0f);
        }
    }
    __syncthreads();
    // spectrum in buf0 is DEAD from here; cumsums alias into it:
    //   cs(s) = (s&2 ? s_im[0] : s_re[0]) + (s&1)*512, 512 entries + total in s_tot[s]

    // ---- 4 parallel exclusive cumsums (warp w -> series w) ----
    if (w < 4) {
        const float* rm = (w & 2) ? &s_im[1][(w & 1) * 512] : &s_re[1][(w & 1) * 512];
        float* cs = ((w & 2) ? &s_im[0][0] : &s_re[0][0]) + (w & 1) * 512;
        int base = lane * 16;
        float run = 0.f, pref[16];
        #pragma unroll
        for (int i = 0; i < 16; i++) { pref[i] = run; run += rm[base + i]; }
        float inc = run;
        #pragma unroll
        for (int sft = 1; sft < 32; sft <<= 1) {
            float v = __shfl_up_sync(0xffffffffu, inc, sft);
            if (lane >= sft) inc += v;
        }
        float excl = inc - run;
        #pragma unroll
        for (int i = 0; i < 16; i++) cs[base + i] = excl + pref[i];
        if (lane == 31) s_tot[w] = inc;
    }
    __syncthreads();

    // ---- trend + W_lin reduce, 4 series ----
    float Wt[6], bt[6];
    #pragma unroll
    for (int j = 0; j < 6; j++) { Wt[j] = W_trend[j]; bt[j] = b_trend[j]; }
    const int   KSv[6] = {4, 8, 12, 16, 24, 32};
    const float inv[6] = {0.25f, 0.125f, 1.f / 12.f, 0.0625f, 1.f / 24.f, 0.03125f};
    float wl0 = W_lin[tid], wl1 = W_lin[tid + 256];

    float accv[4];
    #pragma unroll
    for (int s = 0; s < 4; s++) {
        const float* rem_s = (s & 2) ? &s_im[1][(s & 1) * 512] : &s_re[1][(s & 1) * 512];
        const float* cs_s  = ((s & 2) ? &s_im[0][0] : &s_re[0][0]) + (s & 1) * 512;
        const float* x_s   = s_x[s];
        float tot_s = s_tot[s];
        float rem0 = rem_s[0], remL = rem_s[511];
        float acc = 0.f;
        #pragma unroll
        for (int tt = 0; tt < 2; tt++) {
            int t = tid + tt * 256;
            float rem = rem_s[t];
            float mm[6], lg[6];
            float mx = -FLT_MAX;
            #pragma unroll
            for (int j = 0; j < 6; j++) {
                int k = KSv[j];
                int lo = t - (k >> 1), hi = t + (k >> 1) - 1;
                int clo = lo < 0 ? 0 : lo;
                int chi = hi > 511 ? 511 : hi;
                int ci  = chi > 510 ? 510 : chi;          // clamp for safe aliased load
                float hiv = (chi == 511) ? tot_s : cs_s[ci + 1];
                float ssum = hiv - cs_s[clo];
                if (lo < 0)   ssum += (float)(-lo) * rem0;
                if (hi > 511) ssum += (float)(hi - 511) * remL;
                mm[j] = ssum * inv[j];
                float l = fmaf(rem, Wt[j], bt[j]);
                lg[j] = l;
                mx = fmaxf(mx, l);
            }
            float es = 0.f, ws = 0.f;
            #pragma unroll
            for (int j = 0; j < 6; j++) {
                float e = __expf(lg[j] - mx);
                es += e;
                ws = fmaf(e, mm[j], ws);
            }
            float trend = ws / es;
            float xsum = 2.0f * x_s[t] - rem + trend;
            acc = fmaf(xsum, (tt ? wl1 : wl0), acc);
        }
        accv[s] = acc;
    }

    #pragma unroll
    for (int o = 16; o > 0; o >>= 1) {
        accv[0] += __shfl_down_sync(0xffffffffu, accv[0], o);
        accv[1] += __shfl_down_sync(0xffffffffu, accv[1], o);
        accv[2] += __shfl_down_sync(0xffffffffu, accv[2], o);
        accv[3] += __shfl_down_sync(0xffffffffu, accv[3], o);
    }
    if (lane == 0) {
        s_red[0][w] = accv[0]; s_red[1][w] = accv[1];
        s_red[2][w] = accv[2]; s_red[3][w] = accv[3];
    }
    __syncthreads();
    if (tid < 4) {
        float s = 0.f;
        #pragma unroll
        for (int ww = 0; ww < 8; ww++) s += s_red[tid][ww];
        g_xtr[blockIdx.x * 4 + tid] = s;
    }
}

// ---------------- final routing: (B,D)->(B,8), softplus noise, softmax, top-4 ----------------
__global__ void k_router(const float* __restrict__ noise, const float* __restrict__ W_r,
                         const float* __restrict__ b_r, const float* __restrict__ W_noise,
                         const float* __restrict__ b_noise, const float* __restrict__ b_lin,
                         float* __restrict__ out) {
    int b = blockIdx.x;
    int tid = threadIdx.x;
    int m = tid & 7, c = tid >> 3;
    __shared__ float sp[256], sn[256];
    __shared__ float slog[8];
    const float* xt = g_xtr + b * DD;
    float blin = b_lin[0];
    float p = 0.f, pn = 0.f;
    #pragma unroll
    for (int i = 0; i < 16; i++) {
        int d = c * 16 + i;
        float v = xt[d] + blin;
        p  = fmaf(v, W_r[d * 8 + m], p);
        pn = fmaf(v, W_noise[d * 8 + m], pn);
    }
    sp[tid] = p; sn[tid] = pn;
    __syncthreads();
    if (tid < 8) {
        float P = 0.f, N = 0.f;
        for (int cc = 0; cc < 32; cc++) { P += sp[cc * 8 + tid]; N += sn[cc * 8 + tid]; }
        float base = P + b_r[tid];
        float nl = N + b_noise[tid];
        float ns = log1pf(expf(-fabsf(nl))) + fmaxf(nl, 0.f);   // softplus
        slog[tid] = base + noise[b * 8 + tid] * ns;
    }
    __syncthreads();
    if (tid == 0) {
        float lg[8], mx = -FLT_MAX;
        #pragma unroll
        for (int i = 0; i < 8; i++) { lg[i] = slog[i]; mx = fmaxf(mx, lg[i]); }
        float es = 0.f, pw[8];
        #pragma unroll
        for (int i = 0; i < 8; i++) { pw[i] = expf(lg[i] - mx); es += pw[i]; }
        #pragma unroll
        for (int i = 0; i < 8; i++) pw[i] /= es;
        #pragma unroll
        for (int i = 0; i < 8; i++) {
            int rank = 0;
            #pragma unroll
            for (int j = 0; j < 8; j++)
                if (pw[j] > pw[i] || (pw[j] == pw[i] && j < i)) rank++;
            out[b * 8 + i] = (rank < 4) ? pw[i] : 0.f;
        }
    }
}

// ---------------- launch ----------------
extern "C" void kernel_launch(void* const* d_in, const int* in_sizes, int n_in,
                              void* d_out, int out_size) {
    const float* x       = (const float*)d_in[0];
    const float* noise   = (const float*)d_in[1];
    const float* W_r     = (const float*)d_in[2];
    const float* b_r     = (const float*)d_in[3];
    const float* W_noise = (const float*)d_in[4];
    const float* b_noise = (const float*)d_in[5];
    const float* W_trend = (const float*)d_in[6];
    const float* b_trend = (const float*)d_in[7];
    const float* W_lin   = (const float*)d_in[8];
    const float* b_lin   = (const float*)d_in[9];
    float* out = (float*)d_out;

    k_fused<<<BB * DD / 4, 256>>>(x, W_trend, b_trend, W_lin);
    k_router<<<16, 256>>>(noise, W_r, b_r, W_noise, b_noise, b_lin, out);
}